// round 6
// baseline (speedup 1.0000x reference)
#include <cuda_runtime.h>

#define BB 8
#define CC 512
#define TT 8192
#define OPT 4               // outputs per thread
#define NT 256              // threads per block
#define CHUNK (NT * OPT)    // 1024 outputs per block
#define NCHUNK (TT / CHUNK) // 8 blocks per (b,c) row

// padded smem index: stride 9 words per thread -> conflict-free
__device__ __forceinline__ int zidx(int L) { return L + (L >> 3); }
#define SZF (2057 + (2057 >> 3) + 1)   // 2315 floats

__global__ __launch_bounds__(NT) void aa_fused_kernel(
    const float* __restrict__ x,
    const float* __restrict__ alpha,
    const float* __restrict__ beta,
    const float* __restrict__ fu,
    const float* __restrict__ fd,
    float* __restrict__ out)
{
    __shared__ float s_z[SZF];                  // 9260 B
    __shared__ float s_g0[6], s_g1[6], s_fd[12];
    __shared__ float s_a, s_ib;

    const int tid = threadIdx.x;
    const int bid = blockIdx.x;
    const int row = bid >> 3;       // NCHUNK == 8
    const int chunk = bid & 7;
    const int c = row & (CC - 1);

    // Stage filters (2x upsample gain folded in) + per-channel snake params.
    if (tid < 6)        s_g0[tid] = 2.0f * fu[10 - 2 * tid];                   // odd-n phase
    else if (tid < 12)  { int r = tid - 6; s_g1[r] = 2.0f * fu[11 - 2 * r]; }  // even-n phase
    else if (tid < 24)  s_fd[tid - 12] = fd[tid - 12];
    else if (tid == 24) s_a  = expf(alpha[c]);
    else if (tid == 25) s_ib = 1.0f / (expf(beta[c]) + 1e-9f);
    __syncthreads();

    const float a  = s_a;
    const float ib = s_ib;

    const float* xrow = x + (size_t)row * TT;
    float* orow = out + (size_t)row * TT;
    const int ob = chunk * CHUNK;
    const int tb = ob + tid * OPT;

    // scalar clamped z for edges / block-tail extras; n = upsampled index
    auto zval = [&](int n) -> float {
        n = min(max(n, 0), 2 * TT - 1);
        const int m = n >> 1;
        float acc = 0.0f;
        if (n & 1) {
            #pragma unroll
            for (int r = 0; r < 6; r++) {
                const int j = min(max(m - 2 + r, 0), TT - 1);
                acc += s_g0[r] * __ldg(&xrow[j]);
            }
        } else {
            #pragma unroll
            for (int r = 0; r < 6; r++) {
                const int j = min(max(m - 3 + r, 0), TT - 1);
                acc += s_g1[r] * __ldg(&xrow[j]);
            }
        }
        const float sv = __sinf(acc * a);
        return acc + sv * sv * ib;
    };

    // ---------- Phase A: 8 own z values (z[s] ~ n = 2*tb - 5 + s), publish all ----------
    {
        const int Lb = tid * 8;                  // block-local z index base
        const bool fast = (tb >= 8);             // window x[tb-8 .. tb+3]
        if (fast) {
            float g0r[6], g1r[6];
            #pragma unroll
            for (int r = 0; r < 6; r++) { g0r[r] = s_g0[r]; g1r[r] = s_g1[r]; }
            float xw[12];
            const float4* xv = (const float4*)(xrow + tb - 8);
            #pragma unroll
            for (int i = 0; i < 3; i++) {
                float4 v = xv[i];
                xw[4 * i + 0] = v.x; xw[4 * i + 1] = v.y;
                xw[4 * i + 2] = v.z; xw[4 * i + 3] = v.w;
            }
            #pragma unroll
            for (int s = 0; s < 8; s++) {
                const int h = 3 + (s >> 1);      // window xw[h .. h+5], max 11
                float acc;
                if ((s & 1) == 0) {
                    acc = g0r[0] * xw[h];
                    #pragma unroll
                    for (int r = 1; r < 6; r++) acc += g0r[r] * xw[h + r];
                } else {
                    acc = g1r[0] * xw[h];
                    #pragma unroll
                    for (int r = 1; r < 6; r++) acc += g1r[r] * xw[h + r];
                }
                const float sv = __sinf(acc * a);
                s_z[zidx(Lb + s)] = acc + sv * sv * ib;
            }
        } else {
            // only tb in {0, 4} (chunk 0, threads 0-1): clamped path
            #pragma unroll
            for (int s = 0; s < 8; s++) s_z[zidx(Lb + s)] = zval(2 * tb - 5 + s);
        }
        // block-tail extras: L = 2048..2057 (10 values), threads 0..9
        if (tid < 10) {
            const int L = 2048 + tid;
            s_z[zidx(L)] = zval(2 * ob - 5 + L);
        }
    }
    __syncthreads();

    // ---------- Phase B: downsample from smem ----------
    // out[tb+i] = sum_q fd[q] * z[L = 8*tid + 2i + q]
    float fdr[12];
    #pragma unroll
    for (int q = 0; q < 12; q++) fdr[q] = s_fd[q];

    float Z[18];
    {
        const int Lb = tid * 8;
        #pragma unroll
        for (int s = 0; s < 18; s++) Z[s] = s_z[zidx(Lb + s)];
    }

    float o[OPT];
    #pragma unroll
    for (int i = 0; i < OPT; i++) {
        float acc = fdr[0] * Z[2 * i];
        #pragma unroll
        for (int q = 1; q < 12; q++) acc += fdr[q] * Z[2 * i + q];
        o[i] = acc;
    }
    float4* ov = (float4*)(orow + tb);
    ov[0] = make_float4(o[0], o[1], o[2], o[3]);
}

extern "C" void kernel_launch(void* const* d_in, const int* in_sizes, int n_in,
                              void* d_out, int out_size)
{
    const float* x     = (const float*)d_in[0];
    const float* alpha = (const float*)d_in[1];
    const float* beta  = (const float*)d_in[2];
    const float* fu    = (const float*)d_in[3];
    const float* fd    = (const float*)d_in[4];
    float* out = (float*)d_out;

    const int grid = BB * CC * NCHUNK; // 32768
    aa_fused_kernel<<<grid, NT>>>(x, alpha, beta, fu, fd, out);
}

// round 7
// speedup vs baseline: 1.0936x; 1.0936x over previous
#include <cuda_runtime.h>

#define BB 8
#define CC 512
#define TT 8192
#define OPT 8               // outputs per thread
#define NT 256              // threads per block
#define CHUNK (NT * OPT)    // 2048 outputs per block
#define NCHUNK (TT / CHUNK) // 4 blocks per (b,c) row

__global__ __launch_bounds__(NT) void aa_fused_kernel(
    const float* __restrict__ x,
    const float* __restrict__ alpha,
    const float* __restrict__ beta,
    const float* __restrict__ fu,
    const float* __restrict__ fd,
    float* __restrict__ out)
{
    __shared__ float s_g0[6], s_g1[6], s_fd[12];
    __shared__ float s_a, s_ib;

    const int tid = threadIdx.x;
    const int bid = blockIdx.x;
    const int row = bid >> 2;      // NCHUNK == 4
    const int chunk = bid & 3;
    const int c = row & (CC - 1);

    // Stage filters (2x upsample gain folded in) + per-channel snake params.
    if (tid < 6)        s_g0[tid] = 2.0f * fu[10 - 2 * tid];                   // odd-n phase
    else if (tid < 12)  { int r = tid - 6; s_g1[r] = 2.0f * fu[11 - 2 * r]; }  // even-n phase
    else if (tid < 24)  s_fd[tid - 12] = fd[tid - 12];
    else if (tid == 24) s_a  = expf(alpha[c]);
    else if (tid == 25) s_ib = 1.0f / (expf(beta[c]) + 1e-9f);
    __syncthreads();

    const float a  = s_a;
    const float ib = s_ib;

    const float* xrow = x + (size_t)row * TT;
    float* orow = out + (size_t)row * TT;
    const int tb = chunk * CHUNK + tid * OPT;
    const int lane = tid & 31;

    // clamped scalar z (edge thread + lane-31 halo); n = upsampled index
    auto zval = [&](int n) -> float {
        n = min(max(n, 0), 2 * TT - 1);
        const int m = n >> 1;
        float acc = 0.0f;
        if (n & 1) {
            #pragma unroll
            for (int r = 0; r < 6; r++) {
                const int j = min(max(m - 2 + r, 0), TT - 1);
                acc += s_g0[r] * __ldg(&xrow[j]);
            }
        } else {
            #pragma unroll
            for (int r = 0; r < 6; r++) {
                const int j = min(max(m - 3 + r, 0), TT - 1);
                acc += s_g1[r] * __ldg(&xrow[j]);
            }
        }
        const float sv = __sinf(acc * a);
        return acc + sv * sv * ib;
    };

    // Z[s] ~ upsampled index n = 2*tb - 5 + s. Own: s = 0..15. Halo: s = 16..25
    // equals right-neighbor lane's Z[0..9] (its tb' = tb + 8 -> n = 2*tb + 11 + j).
    float Z[26];

    if (tb >= 8) {
        // fast path: window x[tb-8 .. tb+7] (tb+7 <= 8191 always)
        float g0r[6], g1r[6];
        #pragma unroll
        for (int r = 0; r < 6; r++) { g0r[r] = s_g0[r]; g1r[r] = s_g1[r]; }
        float xw[16];
        const float4* xv = (const float4*)(xrow + tb - 8);
        #pragma unroll
        for (int i = 0; i < 4; i++) {
            float4 v = xv[i];
            xw[4 * i + 0] = v.x; xw[4 * i + 1] = v.y;
            xw[4 * i + 2] = v.z; xw[4 * i + 3] = v.w;
        }
        #pragma unroll
        for (int s = 0; s < 16; s++) {
            const int h = 3 + (s >> 1);          // window xw[h .. h+5], max 15
            float acc;
            if ((s & 1) == 0) {
                acc = g0r[0] * xw[h];
                #pragma unroll
                for (int r = 1; r < 6; r++) acc += g0r[r] * xw[h + r];
            } else {
                acc = g1r[0] * xw[h];
                #pragma unroll
                for (int r = 1; r < 6; r++) acc += g1r[r] * xw[h + r];
            }
            const float sv = __sinf(acc * a);
            Z[s] = acc + sv * sv * ib;
        }
    } else {
        // only thread 0 of chunk 0 (tb == 0): clamped path
        #pragma unroll
        for (int s = 0; s < 16; s++) Z[s] = zval(2 * tb - 5 + s);
    }

    // halo via intra-warp shuffle: Z[16+j] = neighbor lane's Z[j]
    #pragma unroll
    for (int j = 0; j < 10; j++)
        Z[16 + j] = __shfl_down_sync(0xffffffffu, Z[j], 1);
    if (lane == 31) {
        // no in-warp neighbor: recompute (clamped handles row end too)
        #pragma unroll
        for (int j = 0; j < 10; j++) Z[16 + j] = zval(2 * tb + 11 + j);
    }

    // downsample: out[tb+i] = sum_q fd[q] * Z[2i+q]
    float fdr[12];
    #pragma unroll
    for (int q = 0; q < 12; q++) fdr[q] = s_fd[q];

    float o[OPT];
    #pragma unroll
    for (int i = 0; i < OPT; i++) {
        float acc = fdr[0] * Z[2 * i];
        #pragma unroll
        for (int q = 1; q < 12; q++) acc += fdr[q] * Z[2 * i + q];
        o[i] = acc;
    }
    float4* ov = (float4*)(orow + tb);
    ov[0] = make_float4(o[0], o[1], o[2], o[3]);
    ov[1] = make_float4(o[4], o[5], o[6], o[7]);
}

extern "C" void kernel_launch(void* const* d_in, const int* in_sizes, int n_in,
                              void* d_out, int out_size)
{
    const float* x     = (const float*)d_in[0];
    const float* alpha = (const float*)d_in[1];
    const float* beta  = (const float*)d_in[2];
    const float* fu    = (const float*)d_in[3];
    const float* fd    = (const float*)d_in[4];
    float* out = (float*)d_out;

    const int grid = BB * CC * NCHUNK; // 16384
    aa_fused_kernel<<<grid, NT>>>(x, alpha, beta, fu, fd, out);
}

// round 10
// speedup vs baseline: 1.8389x; 1.6815x over previous
#include <cuda_runtime.h>

#define BB 8
#define CC 512
#define TT 8192
#define OPT 16              // outputs per thread
#define NT 128              // threads per block
#define CHUNK (NT * OPT)    // 2048 outputs per block
#define NCHUNK (TT / CHUNK) // 4 blocks per (b,c) row

__global__ __launch_bounds__(NT) void aa_fused_kernel(
    const float* __restrict__ x,
    const float* __restrict__ alpha,
    const float* __restrict__ beta,
    const float* __restrict__ fu,
    const float* __restrict__ fd,
    float* __restrict__ out)
{
    __shared__ float s_g0[6], s_F[6];
    __shared__ float s_a, s_ib;

    const int tid = threadIdx.x;
    const int bid = blockIdx.x;
    const int row = bid >> 2;       // NCHUNK == 4
    const int chunk = bid & 3;
    const int c = row & (CC - 1);

    // g0[r] = 2*fu[10-2r] (odd-n phase). Even-n phase g1[r] == g0[5-r] exactly,
    // because the kaiser filter is symmetric (fu[i] == fu[11-i] bit-exact).
    // Down taps: fd symmetric too; F[d] covers the 6 distinct values:
    //   fd[2d] == F[d], fd[2d+1] == F[5-d].
    if (tid < 6) {
        s_g0[tid] = 2.0f * fu[10 - 2 * tid];
    } else if (tid < 12) {
        const int d = tid - 6;
        const int map[6] = {0, 2, 4, 5, 3, 1};
        s_F[d] = fd[map[d]];
    } else if (tid == 12) {
        s_a = expf(alpha[c]);
    } else if (tid == 13) {
        s_ib = 1.0f / (expf(beta[c]) + 1e-9f);
    }
    __syncthreads();

    float g0r[6], F[6];
    #pragma unroll
    for (int r = 0; r < 6; r++) { g0r[r] = s_g0[r]; F[r] = s_F[r]; }
    const float a  = s_a;
    const float ib = s_ib;

    const float* xrow = x + (size_t)row * TT;
    float* orow = out + (size_t)row * TT;
    const int tb = chunk * CHUNK + tid * OPT;

    const bool elo = (tb == 0);
    const bool ehi = (tb == TT - OPT);   // 8176

    // x window: xq[j] = x[tb-8+j], j=0..31 (compute uses 3..28)
    float xq[32];
    if (!elo && !ehi) {
        const float4* xv = (const float4*)(xrow + tb - 8);
        #pragma unroll
        for (int v = 0; v < 8; v++) {
            float4 q = xv[v];
            xq[4 * v + 0] = q.x; xq[4 * v + 1] = q.y;
            xq[4 * v + 2] = q.z; xq[4 * v + 3] = q.w;
        }
    } else {
        #pragma unroll
        for (int v = 0; v < 8; v++) {
            int base = tb - 8 + 4 * v;
            base = min(max(base, 0), TT - 4);           // legal aligned load
            float4 q = *(const float4*)(xrow + base);
            xq[4 * v + 0] = q.x; xq[4 * v + 1] = q.y;
            xq[4 * v + 2] = q.z; xq[4 * v + 3] = q.w;
        }
        if (elo) {
            const float x0 = xq[8];                     // x[0] (tb==0 -> xq[8]=x[0])
            #pragma unroll
            for (int j = 0; j < 8; j++) xq[j] = x0;     // replicate pad x[-8..-1]
        }
        if (ehi) {
            const float xN = xq[23];                    // x[8191] (tb-8+23)
            #pragma unroll
            for (int j = 24; j < 32; j++) xq[j] = xN;   // replicate pad x[8192..]
        }
    }

    // zlo = z at upsampled index n = 0 (row-left clamp region target)
    float zlo = 0.0f;
    if (elo) {
        const float x0 = xq[8], x1 = xq[9], x2 = xq[10];
        float accl = x0 * (g0r[5] + g0r[4] + g0r[3] + g0r[2])
                   + g0r[1] * x1 + g0r[0] * x2;
        const float sl = __sinf(accl * a);
        zlo = fmaf(sl * sl, ib, accl);
    }

    float o[OPT];
    float zh = 0.0f;

    // Stream z pairs: u = 0..20; z0 = z[s=2u] (odd n, taps g0),
    // z1 = z[s=2u+1] (even n, taps g0 reversed); shared window xq[3+u .. 8+u].
    // n = 2*tb - 5 + s. Scatter: o[u-d] += F[d]*z0 + F[5-d]*z1, d = 0..5.
    #pragma unroll
    for (int u = 0; u < 21; u++) {
        float acc0 = g0r[0] * xq[3 + u];
        float acc1 = g0r[5] * xq[3 + u];
        #pragma unroll
        for (int r = 1; r < 6; r++) {
            acc0 = fmaf(g0r[r],     xq[3 + u + r], acc0);
            acc1 = fmaf(g0r[5 - r], xq[3 + u + r], acc1);
        }
        const float s0 = __sinf(acc0 * a);
        const float s1 = __sinf(acc1 * a);
        float z0 = fmaf(s0 * s0, ib, acc0);
        float z1 = fmaf(s1 * s1, ib, acc1);

        // row-left clamp: s < 5 (n < 0) -> z(n=0)
        if (u == 0) { z0 = elo ? zlo : z0; z1 = elo ? zlo : z1; }
        if (u == 1) { z0 = elo ? zlo : z0; z1 = elo ? zlo : z1; }
        if (u == 2) { z0 = elo ? zlo : z0; }
        // row-right clamp: s > 36 (n > 2T-1) -> z(s=36) == z(n=2T-1) for tb=8176
        if (u == 18) { zh = z0; z1 = ehi ? zh : z1; }
        if (u >= 19) { z0 = ehi ? zh : z0; z1 = ehi ? zh : z1; }

        #pragma unroll
        for (int d = 0; d < 6; d++) {
            const int i = u - d;
            if (i >= 0 && i < OPT) {
                if (d == 0) o[i] = fmaf(F[0], z0, F[5] * z1);
                else        o[i] = fmaf(F[d], z0, fmaf(F[5 - d], z1, o[i]));
            }
        }

        if (u == 8)  *(float4*)(orow + tb)      = make_float4(o[0],  o[1],  o[2],  o[3]);
        if (u == 12) *(float4*)(orow + tb + 4)  = make_float4(o[4],  o[5],  o[6],  o[7]);
        if (u == 16) *(float4*)(orow + tb + 8)  = make_float4(o[8],  o[9],  o[10], o[11]);
        if (u == 20) *(float4*)(orow + tb + 12) = make_float4(o[12], o[13], o[14], o[15]);
    }
}

extern "C" void kernel_launch(void* const* d_in, const int* in_sizes, int n_in,
                              void* d_out, int out_size)
{
    const float* x     = (const float*)d_in[0];
    const float* alpha = (const float*)d_in[1];
    const float* beta  = (const float*)d_in[2];
    const float* fu    = (const float*)d_in[3];
    const float* fd    = (const float*)d_in[4];
    float* out = (float*)d_out;

    const int grid = BB * CC * NCHUNK; // 16384
    aa_fused_kernel<<<grid, NT>>>(x, alpha, beta, fu, fd, out);
}